// round 7
// baseline (speedup 1.0000x reference)
#include <cuda_runtime.h>

// Problem constants (VisualPromptEncoder_49074296324730)
#define BB    8
#define CC    256
#define HH    160
#define WW    160
#define NN    100    // boxes per image
#define NCLS  80     // classes
#define TROWS 16     // tile rows
#define NTILE 10     // HH / TROWS
#define PSTR  164    // padded row stride (mult of 4, conflict-free)
#define THR1  256    // 8 warps
#define NCOR  (4 * NN)

// ---------------------------------------------------------------------------
// One block per (b,c) plane. Double-buffered row scan (registers->smem once),
// column scan keeps running SAT in registers and captures corner values
// inline (no SAT write-back, no harvest pass). Fused class-mean epilogue.
// ---------------------------------------------------------------------------
__global__ void __launch_bounds__(THR1, 6)
vpe_fused_kernel(const float* __restrict__ feat,
                 const float* __restrict__ boxes,
                 const int*   __restrict__ gtc,
                 const int*   __restrict__ neg_y,
                 const int*   __restrict__ neg_x,
                 const int*   __restrict__ img_h,
                 const int*   __restrict__ img_w,
                 float*       __restrict__ out)
{
    __shared__ float buf[2][TROWS * PSTR]; // double-buffered scanned rows
    __shared__ float cv[NCOR];             // corner SAT values
    __shared__ short cyv[NCOR];            // corner y (0..160)
    __shared__ short cxv[NCOR];            // corner x (0..160)
    __shared__ int   s_cls[NN];            // class per box (-1 invalid)
    __shared__ float s_pool[NN];           // pooled value per box
    __shared__ int   colcnt[WW];           // corners per column (x-1)
    __shared__ int   colstart[WW];         // exclusive prefix
    __shared__ int   colfill[WW];          // scatter cursor
    __shared__ short ccrow[NCOR];          // corner row (y-1), bucketed by col
    __shared__ short ccid[NCOR];           // corner id, bucketed by col

    const int blk  = blockIdx.x;           // b*CC + c
    const int b    = blk >> 8;
    const int c    = blk & 255;
    const int tid  = threadIdx.x;          // 0..255
    const int w    = tid >> 5;             // warp 0..7
    const int lane = tid & 31;

    // ---- setup: corners, classes ----
    #pragma unroll
    for (int j = tid; j < NCOR; j += THR1) cv[j] = 0.f;
    if (tid < WW) { colcnt[tid] = 0; colfill[tid] = 0; }
    if (tid < NN) {
        const float sx = (float)WW / (float)img_w[0];
        const float sy = (float)HH / (float)img_h[0];
        const float* bx = boxes + ((size_t)b * NN + tid) * 4;
        const int x1 = (int)fminf(fmaxf(floorf(bx[0] * sx), 0.f), (float)WW);
        const int y1 = (int)fminf(fmaxf(floorf(bx[1] * sy), 0.f), (float)HH);
        const int x2 = (int)fminf(fmaxf(floorf(bx[2] * sx), 0.f), (float)WW);
        const int y2 = (int)fminf(fmaxf(floorf(bx[3] * sy), 0.f), (float)HH);
        cyv[tid          ] = (short)y2; cxv[tid          ] = (short)x2;  // s22
        cyv[tid +     NN ] = (short)y1; cxv[tid +     NN ] = (short)x2;  // s12
        cyv[tid + 2 * NN ] = (short)y2; cxv[tid + 2 * NN ] = (short)x1;  // s21
        cyv[tid + 3 * NN ] = (short)y1; cxv[tid + 3 * NN ] = (short)x1;  // s11
        s_cls[tid] = ((x2 > x1) && (y2 > y1)) ? gtc[b * NN + tid] : -1;
    }
    __syncthreads();

    // ---- histogram corners by column (col = x-1) ----
    #pragma unroll
    for (int j = tid; j < NCOR; j += THR1) {
        const int y = cyv[j], x = cxv[j];
        if (y >= 1 && x >= 1) atomicAdd(&colcnt[x - 1], 1);
    }
    __syncthreads();

    // ---- exclusive prefix over 160 columns (warp 0, lane owns 5 cols) ----
    if (w == 0) {
        int c0 = colcnt[5 * lane + 0], c1 = colcnt[5 * lane + 1];
        int c2 = colcnt[5 * lane + 2], c3 = colcnt[5 * lane + 3];
        int c4 = colcnt[5 * lane + 4];
        const int t = c0 + c1 + c2 + c3 + c4;
        int it = t;
        #pragma unroll
        for (int d = 1; d < 32; d <<= 1) {
            const int o = __shfl_up_sync(0xffffffffu, it, d);
            if (lane >= d) it += o;
        }
        int e = it - t;
        colstart[5 * lane + 0] = e; e += c0;
        colstart[5 * lane + 1] = e; e += c1;
        colstart[5 * lane + 2] = e; e += c2;
        colstart[5 * lane + 3] = e; e += c3;
        colstart[5 * lane + 4] = e;
    }
    __syncthreads();

    // ---- scatter corner (row,id) into column buckets ----
    #pragma unroll
    for (int j = tid; j < NCOR; j += THR1) {
        const int y = cyv[j], x = cxv[j];
        if (y >= 1 && x >= 1) {
            const int pos = colstart[x - 1] + atomicAdd(&colfill[x - 1], 1);
            ccrow[pos] = (short)(y - 1);
            ccid[pos]  = (short)j;
        }
    }
    __syncthreads();

    // ---- sort each column bucket by row (buckets are tiny) ----
    if (tid < WW) {
        const int s0 = colstart[tid], e0 = s0 + colcnt[tid];
        for (int i = s0 + 1; i < e0; i++) {
            const short rw = ccrow[i], id = ccid[i];
            int k = i - 1;
            while (k >= s0 && ccrow[k] > rw) {
                ccrow[k + 1] = ccrow[k]; ccid[k + 1] = ccid[k]; k--;
            }
            ccrow[k + 1] = rw; ccid[k + 1] = id;
        }
    }

    const float4* plane4 = (const float4*)(feat + (size_t)blk * (HH * WW));

    // column-scan persistent state (threads 0..159 own column tid)
    float run = 0.f;
    int   p = 0, pe = 0, nr = 0x7fff;
    if (tid < WW) {
        p  = colstart[tid];
        pe = p + colcnt[tid];
        nr = (p < pe) ? (int)ccrow[p] : 0x7fff;
    }
    __syncthreads();

    // ---- row scan of one tile into buf[t&1]: warp w rows {w, w+8} ----
    #define ROWSCAN(T)                                                        \
    {                                                                         \
        float* bufp = buf[(T) & 1];                                           \
        _Pragma("unroll")                                                     \
        for (int q = 0; q < 2; q++) {                                         \
            const int r = w + 8 * q;                                          \
            const float4* row4 = plane4 + (size_t)((T) * TROWS + r) * 40;     \
            float4 a = row4[lane];                                            \
            float4 bb = (lane < 8) ? row4[32 + lane]                          \
                                   : make_float4(0.f, 0.f, 0.f, 0.f);         \
            a.y += a.x; a.z += a.y; a.w += a.z;                               \
            bb.y += bb.x; bb.z += bb.y; bb.w += bb.z;                         \
            const float ta = a.w, tb = bb.w;                                  \
            float ia = ta;                                                    \
            _Pragma("unroll")                                                 \
            for (int d = 1; d < 32; d <<= 1) {                                \
                const float o = __shfl_up_sync(0xffffffffu, ia, d);           \
                if (lane >= d) ia += o;                                       \
            }                                                                 \
            const float ea = ia - ta;                                         \
            const float T0 = __shfl_sync(0xffffffffu, ia, 31);                \
            float ib = tb;                                                    \
            _Pragma("unroll")                                                 \
            for (int d = 1; d < 8; d <<= 1) {                                 \
                const float o = __shfl_up_sync(0xffffffffu, ib, d);           \
                if (lane >= d) ib += o;                                       \
            }                                                                 \
            const float eb = T0 + (ib - tb);                                  \
            float* dst = &bufp[r * PSTR];                                     \
            *(float4*)&dst[4 * lane] =                                        \
                make_float4(a.x + ea, a.y + ea, a.z + ea, a.w + ea);          \
            if (lane < 8)                                                     \
                *(float4*)&dst[128 + 4 * lane] =                              \
                    make_float4(bb.x + eb, bb.y + eb, bb.z + eb, bb.w + eb);  \
        }                                                                     \
    }

    ROWSCAN(0);
    __syncthreads();

    for (int t = 0; t < NTILE; t++) {
        if (t < NTILE - 1) ROWSCAN(t + 1);

        // ---- column scan of tile t with inline corner capture ----
        if (tid < WW) {
            const float* bp = buf[t & 1];
            #pragma unroll
            for (int ry = 0; ry < TROWS; ry++) {
                run += bp[ry * PSTR + tid];
                const int gr = t * TROWS + ry;
                while (gr == nr) {                 // rare
                    cv[ccid[p]] = run;
                    p++;
                    nr = (p < pe) ? (int)ccrow[p] : 0x7fff;
                }
            }
        }
        __syncthreads();
    }

    // ---- pooled value per box ----
    if (tid < NN) {
        const int x2 = cxv[tid], y2 = cyv[tid];
        const int x1 = cxv[tid + 2 * NN], y1 = cyv[tid + NN];
        float pv = 0.f;
        if (x2 > x1 && y2 > y1) {
            const float sum = cv[tid] - cv[tid + NN] - cv[tid + 2 * NN] + cv[tid + 3 * NN];
            int area = (x2 - x1) * (y2 - y1);
            if (area < 1) area = 1;
            pv = sum / (float)area;
        }
        s_pool[tid] = pv;
    }
    __syncthreads();

    // ---- per-class mean + negative fallback ----
    if (tid < NCLS) {
        const int cls = tid;
        float sum = 0.f;
        int   cnt = 0;
        #pragma unroll 4
        for (int n = 0; n < NN; n++) {
            if (s_cls[n] == cls) { sum += s_pool[n]; cnt++; }
        }
        float r;
        if (cnt > 0) {
            r = sum / (float)cnt;
        } else {
            const int ny = neg_y[b * NCLS + cls];
            const int nx = neg_x[b * NCLS + cls];
            r = feat[(((size_t)b * CC + c) * HH + ny) * WW + nx];
        }
        out[((size_t)b * NCLS + cls) * CC + c] = r;
    }
}

// ---------------------------------------------------------------------------
extern "C" void kernel_launch(void* const* d_in, const int* in_sizes, int n_in,
                              void* d_out, int out_size)
{
    const float* feat  = (const float*)d_in[0];   // [8,256,160,160] f32
    const float* boxes = (const float*)d_in[1];   // [8,100,4] f32
    const int*   gtc   = (const int*)d_in[2];     // [8,100] i32
    const int*   ngy   = (const int*)d_in[3];     // [8,80] i32
    const int*   ngx   = (const int*)d_in[4];     // [8,80] i32
    const int*   ih    = (const int*)d_in[5];     // scalar
    const int*   iw    = (const int*)d_in[6];     // scalar
    float*       out   = (float*)d_out;           // [8,80,256] f32

    vpe_fused_kernel<<<BB * CC, THR1>>>(feat, boxes, gtc, ngy, ngx, ih, iw, out);
}

// round 8
// speedup vs baseline: 1.5449x; 1.5449x over previous
#include <cuda_runtime.h>

// Problem constants (VisualPromptEncoder_49074296324730)
#define BB    8
#define CC    256
#define HH    160
#define WW    160
#define NN    100    // boxes per image
#define NCLS  80     // classes
#define TROWS 32     // tile rows
#define NTILE 5      // HH / TROWS
#define PSTR  164    // padded row stride (mult of 4, conflict-free)
#define THR1  256    // 8 warps

// ---------------------------------------------------------------------------
// One block per (b,c) plane. Register row-scan from coalesced LDG -> one smem
// write per row. NO column scan / NO SAT: 2 threads per box accumulate
// row-range sums  rp[y][x2-1] - rp[y][x1-1]  straight from the scanned rows.
// Double-buffered tiles, 1 barrier per phase. Fused class-mean epilogue.
// ---------------------------------------------------------------------------
__global__ void __launch_bounds__(THR1, 5)
vpe_fused_kernel(const float* __restrict__ feat,
                 const float* __restrict__ boxes,
                 const int*   __restrict__ gtc,
                 const int*   __restrict__ neg_y,
                 const int*   __restrict__ neg_x,
                 const int*   __restrict__ img_h,
                 const int*   __restrict__ img_w,
                 float*       __restrict__ out)
{
    __shared__ float buf[2][TROWS * PSTR]; // double-buffered scanned rows
    __shared__ short sx1[NN], sx2[NN], sy1[NN], sy2[NN];
    __shared__ int   s_cls[NN];            // class per box (-1 invalid)
    __shared__ float s_acc[2 * NN];        // per (box, half) partial sums
    __shared__ float s_pool[NN];           // pooled value per box

    const int blk  = blockIdx.x;           // b*CC + c
    const int b    = blk >> 8;
    const int c    = blk & 255;
    const int tid  = threadIdx.x;          // 0..255
    const int w    = tid >> 5;             // warp 0..7
    const int lane = tid & 31;

    // ---- setup: box coords + classes ----
    if (tid < NN) {
        const float sx = (float)WW / (float)img_w[0];
        const float sy = (float)HH / (float)img_h[0];
        const float* bx = boxes + ((size_t)b * NN + tid) * 4;
        const int x1 = (int)fminf(fmaxf(floorf(bx[0] * sx), 0.f), (float)WW);
        const int y1 = (int)fminf(fmaxf(floorf(bx[1] * sy), 0.f), (float)HH);
        const int x2 = (int)fminf(fmaxf(floorf(bx[2] * sx), 0.f), (float)WW);
        const int y2 = (int)fminf(fmaxf(floorf(bx[3] * sy), 0.f), (float)HH);
        sx1[tid] = (short)x1; sx2[tid] = (short)x2;
        sy1[tid] = (short)y1; sy2[tid] = (short)y2;
        s_cls[tid] = ((x2 > x1) && (y2 > y1)) ? gtc[b * NN + tid] : -1;
    }
    __syncthreads();

    // ---- event-thread registers: 2 threads per box (even/odd rows) ----
    const bool evt = (tid < 2 * NN);
    int  e_n = 0, e_y1h = 0, e_y2 = 0, e_ax1 = 0, e_ax2 = 0;
    float e_m1 = 0.f;
    bool e_valid = false;
    if (evt) {
        const int n = (tid < NN) ? tid : tid - NN;
        const int h = (tid < NN) ? 0 : 1;
        const int x1 = sx1[n], x2 = sx2[n];
        const int y1 = sy1[n], y2 = sy2[n];
        e_n = n;
        e_valid = (x2 > x1) && (y2 > y1);
        e_y1h = y1 + h;                 // this thread's first row (step 2)
        e_y2  = y2;
        e_ax2 = x2 - 1;
        e_ax1 = (x1 > 0) ? (x1 - 1) : 0;
        e_m1  = (x1 > 0) ? 1.f : 0.f;
    }
    float acc = 0.f;

    const float4* plane4 = (const float4*)(feat + (size_t)blk * (HH * WW));

    // ---- row scan of one tile into buf[T&1]: warp w rows w+8q, q=0..3 ----
    #define ROWSCAN(T)                                                        \
    {                                                                         \
        float* bufp = buf[(T) & 1];                                           \
        _Pragma("unroll")                                                     \
        for (int q = 0; q < 4; q++) {                                         \
            const int r = w + 8 * q;                                          \
            const float4* row4 = plane4 + (size_t)((T) * TROWS + r) * 40;     \
            float4 a = row4[lane];                                            \
            float4 bb = (lane < 8) ? row4[32 + lane]                          \
                                   : make_float4(0.f, 0.f, 0.f, 0.f);         \
            a.y += a.x; a.z += a.y; a.w += a.z;                               \
            bb.y += bb.x; bb.z += bb.y; bb.w += bb.z;                         \
            const float ta = a.w, tb = bb.w;                                  \
            float ia = ta;                                                    \
            _Pragma("unroll")                                                 \
            for (int d = 1; d < 32; d <<= 1) {                                \
                const float o = __shfl_up_sync(0xffffffffu, ia, d);           \
                if (lane >= d) ia += o;                                       \
            }                                                                 \
            const float ea = ia - ta;                                         \
            const float T0 = __shfl_sync(0xffffffffu, ia, 31);                \
            float ib = tb;                                                    \
            _Pragma("unroll")                                                 \
            for (int d = 1; d < 8; d <<= 1) {                                 \
                const float o = __shfl_up_sync(0xffffffffu, ib, d);           \
                if (lane >= d) ib += o;                                       \
            }                                                                 \
            const float eb = T0 + (ib - tb);                                  \
            float* dst = &bufp[r * PSTR];                                     \
            *(float4*)&dst[4 * lane] =                                        \
                make_float4(a.x + ea, a.y + ea, a.z + ea, a.w + ea);          \
            if (lane < 8)                                                     \
                *(float4*)&dst[128 + 4 * lane] =                              \
                    make_float4(bb.x + eb, bb.y + eb, bb.z + eb, bb.w + eb);  \
        }                                                                     \
    }

    ROWSCAN(0);
    __syncthreads();

    for (int t = 0; t < NTILE; t++) {
        if (t < NTILE - 1) ROWSCAN(t + 1);

        // ---- accumulate row-range sums for tile t ----
        if (evt & e_valid) {
            const int tlo = t * TROWS;
            const int thi = tlo + TROWS;
            // first row >= tlo with row = e_y1h + 2k
            int start = e_y1h;
            const int d0 = tlo - e_y1h;
            if (d0 > 0) start = e_y1h + ((d0 + 1) & ~1);
            const int hi = (e_y2 < thi) ? e_y2 : thi;
            const float* bp = buf[t & 1];
            for (int y = start; y < hi; y += 2) {
                const float* rp = bp + (y - tlo) * PSTR;
                acc += rp[e_ax2] - e_m1 * rp[e_ax1];
            }
        }
        __syncthreads();
    }

    if (evt) s_acc[tid] = acc;
    __syncthreads();

    // ---- pooled value per box ----
    if (tid < NN) {
        const int x1 = sx1[tid], x2 = sx2[tid];
        const int y1 = sy1[tid], y2 = sy2[tid];
        float pv = 0.f;
        if (x2 > x1 && y2 > y1) {
            const float sum = s_acc[tid] + s_acc[tid + NN];
            int area = (x2 - x1) * (y2 - y1);
            if (area < 1) area = 1;
            pv = sum / (float)area;
        }
        s_pool[tid] = pv;
    }
    __syncthreads();

    // ---- per-class mean + negative fallback ----
    if (tid < NCLS) {
        const int cls = tid;
        float sum = 0.f;
        int   cnt = 0;
        #pragma unroll 4
        for (int n = 0; n < NN; n++) {
            if (s_cls[n] == cls) { sum += s_pool[n]; cnt++; }
        }
        float r;
        if (cnt > 0) {
            r = sum / (float)cnt;
        } else {
            const int ny = neg_y[b * NCLS + cls];
            const int nx = neg_x[b * NCLS + cls];
            r = feat[(((size_t)b * CC + c) * HH + ny) * WW + nx];
        }
        out[((size_t)b * NCLS + cls) * CC + c] = r;
    }
}

// ---------------------------------------------------------------------------
extern "C" void kernel_launch(void* const* d_in, const int* in_sizes, int n_in,
                              void* d_out, int out_size)
{
    const float* feat  = (const float*)d_in[0];   // [8,256,160,160] f32
    const float* boxes = (const float*)d_in[1];   // [8,100,4] f32
    const int*   gtc   = (const int*)d_in[2];     // [8,100] i32
    const int*   ngy   = (const int*)d_in[3];     // [8,80] i32
    const int*   ngx   = (const int*)d_in[4];     // [8,80] i32
    const int*   ih    = (const int*)d_in[5];     // scalar
    const int*   iw    = (const int*)d_in[6];     // scalar
    float*       out   = (float*)d_out;           // [8,80,256] f32

    vpe_fused_kernel<<<BB * CC, THR1>>>(feat, boxes, gtc, ngy, ngx, ih, iw, out);
}